// round 16
// baseline (speedup 1.0000x reference)
#include <cuda_runtime.h>
#include <cuda_fp16.h>
#include <math.h>

// ---------------------------------------------------------------------------
// DRR ray integration, GB300.
// g_vol[z][y][x] holds a 2x2 (x,y)-face quad of the regulated density,
// quantized to u8:  u = round( v * 255/0.65 ),  v = sigmoid(d - 0.3).
//   quad bytes = ( u(x,y), u(x+1,y), u(x,y+1), u(x+1,y+1) )  in one uint.
// One trilinear tap = 2 x LDG.32 (faces at z and z+1); 70 MB volume is
// mostly L2-resident. u=0 maps to v=0 so zero-padded borders are exact.
// drr: one warp per ray; __launch_bounds__(256,8) caps regs at 32 so 2048
// threads/SM are resident (64 warps) to hide L2 latency.
// pack: float4 reads + tanh-sigmoid + word STS; write phase assembles
// quads from smem words via PRMT.
// ---------------------------------------------------------------------------

#define DIM 256
#define PITCH 260
#define PITCH2 (PITCH * PITCH)

#define V_SCALE (0.65f / 255.0f)      // v = u * V_SCALE
#define U_SCALE (255.0f / 0.65f)      // u = v * U_SCALE

__device__ unsigned g_vol[PITCH * PITCH * PITCH];  // ~70 MB, .bss zero-init
__device__ float    g_inv[12];                      // inv(affine)[:3,:4]

// ---------------------------------------------------------------------------
// 4x4 Gauss-Jordan inverse (single thread; runs inside pack kernel).
// ---------------------------------------------------------------------------
__device__ void invert_affine(const float* __restrict__ A) {
    float m[4][8];
#pragma unroll
    for (int r = 0; r < 4; r++)
#pragma unroll
        for (int c = 0; c < 4; c++) {
            m[r][c]     = A[r * 4 + c];
            m[r][c + 4] = (r == c) ? 1.0f : 0.0f;
        }
    for (int col = 0; col < 4; col++) {
        int piv = col;
        float best = fabsf(m[col][col]);
        for (int r = col + 1; r < 4; r++) {
            float v = fabsf(m[r][col]);
            if (v > best) { best = v; piv = r; }
        }
        if (piv != col)
            for (int c = 0; c < 8; c++) {
                float t = m[col][c]; m[col][c] = m[piv][c]; m[piv][c] = t;
            }
        float d = 1.0f / m[col][col];
        for (int c = 0; c < 8; c++) m[col][c] *= d;
        for (int r = 0; r < 4; r++) {
            if (r == col) continue;
            float f = m[r][col];
            for (int c = 0; c < 8; c++) m[r][c] -= f * m[col][c];
        }
    }
    for (int r = 0; r < 3; r++)
        for (int c = 0; c < 4; c++)
            g_inv[r * 4 + c] = m[r][c + 4];
}

// sigmoid(d - 0.3) via hardware tanh: sig = 0.5*tanh((d-0.3)/2) + 0.5
__device__ __forceinline__ float sig_fast(float d) {
    float t;
    asm("tanh.approx.f32 %0, %1;" : "=f"(t) : "f"(0.5f * (d - 0.3f)));
    return fmaf(0.5f, t, 0.5f);
}

__device__ __forceinline__ unsigned q8f(float v) {
    int u = __float2int_rn(v * U_SCALE);
    return (unsigned)min(max(u, 0), 255);
}

// pack 4 density floats -> 4 quantized bytes in one u32 (z, z+1, z+2, z+3)
__device__ __forceinline__ unsigned quant4(float4 f) {
    unsigned u0 = q8f(sig_fast(f.x));
    unsigned u1 = q8f(sig_fast(f.y));
    unsigned u2 = q8f(sig_fast(f.z));
    unsigned u3 = q8f(sig_fast(f.w));
    return u0 | (u1 << 8) | (u2 << 16) | (u3 << 24);
}

// ---------------------------------------------------------------------------
// Pack kernel: sigmoid + quantize + transpose + (x,y)-face u8-quad pack.
// Flat 256 threads. Tile x:32 (+1 halo), z:32, y:8 (+1 halo plane).
// grid = (8 x-tiles, 8 z-tiles, 32 y-groups).
// Read phase: float4 LDG (4 z at once), 3 planes batched for MLP, word STS.
// Write phase: word LDS + PRMT quad assembly (no byte-LDS).
// ---------------------------------------------------------------------------
__global__ void pack_kernel(const float* __restrict__ dens,
                            const float* __restrict__ affine) {
    int tid = threadIdx.x;
    if (blockIdx.x == 0 && blockIdx.y == 0 && blockIdx.z == 0 && tid == 0)
        invert_affine(affine);

    __shared__ unsigned char s8[9][33][36];  // [yl][x-local][z-local(pad 36)]
    const int x0 = blockIdx.x * 32;
    const int z0 = blockIdx.y * 32;
    const int y0 = blockIdx.z * 8;

    const int row   = tid >> 3;   // 0..31 : x-local row
    const int chunk = tid & 7;    // 0..7  : z float4 chunk

    // --- read phase: 9 y-planes in 3 groups of 3; each group keeps 3 (+1
    // halo) independent float4 loads in flight before any consumes. ---
#pragma unroll
    for (int yg = 0; yg < 3; yg++) {
        float4 v[3];
        float4 vh[3];
        bool ok[3], okh[3];
#pragma unroll
        for (int j = 0; j < 3; j++) {
            int yl = yg * 3 + j;
            int y  = y0 + yl;
            bool yok = (y < DIM);
            int x = x0 + row;
            ok[j] = yok;
            v[j] = ok[j]
                 ? *reinterpret_cast<const float4*>(
                       dens + ((x * DIM) + y) * DIM + z0 + 4 * chunk)
                 : make_float4(1e30f, 1e30f, 1e30f, 1e30f);
            if (tid < 8) {  // halo row x = x0 + 32
                int xh = x0 + 32;
                okh[j] = yok && (xh < DIM);
                vh[j] = okh[j]
                      ? *reinterpret_cast<const float4*>(
                            dens + ((xh * DIM) + y) * DIM + z0 + 4 * tid)
                      : make_float4(1e30f, 1e30f, 1e30f, 1e30f);
            }
        }
#pragma unroll
        for (int j = 0; j < 3; j++) {
            int yl = yg * 3 + j;
            unsigned w = ok[j] ? quant4(v[j]) : 0u;
            *reinterpret_cast<unsigned*>(&s8[yl][row][4 * chunk]) = w;
            if (tid < 8) {
                unsigned wh = okh[j] ? quant4(vh[j]) : 0u;
                *reinterpret_cast<unsigned*>(&s8[yl][32][4 * tid]) = wh;
            }
        }
    }
    __syncthreads();

    // --- write phase: word LDS + PRMT quad assembly ---
    const unsigned* W = reinterpret_cast<const unsigned*>(s8);
    const int tx = tid & 31;      // x lane (coalesced STG)
    const int zw = tid >> 5;      // 0..7 : z word (4 z-values)

#pragma unroll
    for (int yl = 0; yl < 8; yl++) {
        int yp = y0 + yl + 2;
        unsigned w0 = W[(yl * 33 + tx) * 9 + zw];            // (x  , yl  )
        unsigned w1 = W[(yl * 33 + tx + 1) * 9 + zw];        // (x+1, yl  )
        unsigned w2 = W[((yl + 1) * 33 + tx) * 9 + zw];      // (x  , yl+1)
        unsigned w3 = W[((yl + 1) * 33 + tx + 1) * 9 + zw];  // (x+1, yl+1)
#pragma unroll
        for (int k = 0; k < 4; k++) {
            int z = 4 * zw + k;
            int o = ((z0 + z + 2) * PITCH + yp) * PITCH;
            unsigned sel = 0x40u + 0x11u * (unsigned)k;  // {4+k, k}
            unsigned lo = __byte_perm(w0, w1, sel);      // (b0, b1)
            unsigned hi = __byte_perm(w2, w3, sel);      // (b2, b3)
            g_vol[o + x0 + tx + 2] = __byte_perm(lo, hi, 0x5410);
            if (x0 == 0 && tx == 0) {  // padded x=1: orig x=-1 pair
                unsigned b1 = (w0 >> (8 * k)) & 0xFFu;
                unsigned b3 = (w2 >> (8 * k)) & 0xFFu;
                g_vol[o + 1] = (b1 << 8) | (b3 << 24);
            }
        }
    }
    // padded y=1 row (orig y=-1): quad = (0,0, v(x,0), v(x+1,0))
    if (y0 == 0) {
        unsigned w2 = W[(0 * 33 + tx) * 9 + zw];
        unsigned w3 = W[(0 * 33 + tx + 1) * 9 + zw];
#pragma unroll
        for (int k = 0; k < 4; k++) {
            int z = 4 * zw + k;
            int o = ((z0 + z + 2) * PITCH + 1) * PITCH;
            unsigned sel = 0x40u + 0x11u * (unsigned)k;
            unsigned hi = __byte_perm(w2, w3, sel);
            g_vol[o + x0 + tx + 2] = hi << 16;
            if (x0 == 0 && tx == 0) {
                unsigned b3 = (w2 >> (8 * k)) & 0xFFu;
                g_vol[o + 1] = (b3 << 24);
            }
        }
    }
}

// ---------------------------------------------------------------------------
// Ray march: ONE WARP PER RAY. Lane l takes samples p = plo+l, plo+l+32, ...
// Warp-uniform loop bounds, 2 x LDG.32 per tap, PRMT u8->half decode, fp32
// lerp, full-warp shfl reduce. __launch_bounds__(256,8) -> <=32 regs ->
// 2048 threads/SM resident (occupancy-driven latency hiding).
// ---------------------------------------------------------------------------
__global__ void __launch_bounds__(256, 8)
drr_kernel(const float* __restrict__ src,
           const float* __restrict__ tgt,
           const int* __restrict__ npts,
           float* __restrict__ out,
           int nrays) {
    int t    = blockIdx.x * blockDim.x + threadIdx.x;
    int ray  = t >> 5;          // one warp per ray
    int lane = t & 31;
    bool valid = (ray < nrays);

    float acc = 0.0f;       // accumulates w = 1024 + lerp(u)
    float raylen = 0.0f;
    float nin = 0.0f;       // in-box sample count (warp-uniform)
    int P = 500;

    if (valid) {
        P = npts[0];
        float Sx = src[ray * 3 + 0], Sy = src[ray * 3 + 1], Sz = src[ray * 3 + 2];
        float Tx = tgt[ray * 3 + 0], Ty = tgt[ray * 3 + 1], Tz = tgt[ray * 3 + 2];

        float wx = Tx - Sx, wy = Ty - Sy, wz = Tz - Sz;
        raylen = sqrtf(wx * wx + wy * wy + wz * wz);

        // world -> voxel index space
        float sx = g_inv[0] * Sx + g_inv[1] * Sy + g_inv[2]  * Sz + g_inv[3];
        float sy = g_inv[4] * Sx + g_inv[5] * Sy + g_inv[6]  * Sz + g_inv[7];
        float sz = g_inv[8] * Sx + g_inv[9] * Sy + g_inv[10] * Sz + g_inv[11];
        float ex = g_inv[0] * Tx + g_inv[1] * Ty + g_inv[2]  * Tz + g_inv[3];
        float ey = g_inv[4] * Tx + g_inv[5] * Ty + g_inv[6]  * Tz + g_inv[7];
        float ez = g_inv[8] * Tx + g_inv[9] * Ty + g_inv[10] * Tz + g_inv[11];

        float dx = ex - sx, dy = ey - sy, dz = ez - sz;

        // slab-clip alpha to open support box (-1, 256), slightly widened
        float a0 = 0.0f, a1 = 1.0f;
        {
            const float lo = -1.002f, hi = 256.002f;
            float ss[3] = {sx, sy, sz};
            float dd[3] = {dx, dy, dz};
#pragma unroll
            for (int ax = 0; ax < 3; ax++) {
                float s = ss[ax], d = dd[ax];
                if (fabsf(d) < 1e-12f) {
                    if (s <= lo || s >= hi) { a0 = 1.0f; a1 = 0.0f; }
                } else {
                    float inv = 1.0f / d;
                    float ta = (lo - s) * inv;
                    float tb = (hi - s) * inv;
                    a0 = fmaxf(a0, fminf(ta, tb));
                    a1 = fminf(a1, fmaxf(ta, tb));
                }
            }
        }

        float invPm1 = 1.0f / (float)(P - 1);
        int plo = max(0, (int)ceilf(a0 * (float)(P - 1)));
        int phi = min(P - 1, (int)floorf(a1 * (float)(P - 1)));

        if (phi >= plo) {
            nin = (float)(phi - plo + 1);
            float sx2 = sx + 2.0f, sy2 = sy + 2.0f, sz2 = sz + 2.0f;

#pragma unroll 4
            for (int p = plo + lane; p <= phi; p += 32) {
                float a = (float)p * invPm1;
                float X = fmaf(a, dx, sx2);
                float Y = fmaf(a, dy, sy2);
                float Z = fmaf(a, dz, sz2);

                // coords >= ~1 by the clip, so trunc == floor
                int ix = (int)X, iy = (int)Y, iz = (int)Z;
                float ux = X - (float)ix;
                float uy = Y - (float)iy;
                float uz = Z - (float)iz;

                int base = (iz * PITCH + iy) * PITCH + ix;
                unsigned q0 = __ldg(&g_vol[base]);            // face at z
                unsigned q1 = __ldg(&g_vol[base + PITCH2]);   // face at z+1

                // PRMT: half2(1024+b0, 1024+b1) and half2(1024+b2, 1024+b3)
                unsigned p00 = __byte_perm(q0, 0x64646464u, 0x5140);
                unsigned p01 = __byte_perm(q0, 0x64646464u, 0x5342);
                unsigned p10 = __byte_perm(q1, 0x64646464u, 0x5140);
                unsigned p11 = __byte_perm(q1, 0x64646464u, 0x5342);

                float2 a00 = __half22float2(*reinterpret_cast<__half2*>(&p00));
                float2 a01 = __half22float2(*reinterpret_cast<__half2*>(&p01));
                float2 b00 = __half22float2(*reinterpret_cast<__half2*>(&p10));
                float2 b01 = __half22float2(*reinterpret_cast<__half2*>(&p11));

                // lerp x within pairs (w-scale, offset 1024 is lerp-invariant)
                float c0 = fmaf(ux, a00.y - a00.x, a00.x);  // (y  , z  )
                float c1 = fmaf(ux, a01.y - a01.x, a01.x);  // (y+1, z  )
                float d0 = fmaf(ux, b00.y - b00.x, b00.x);  // (y  , z+1)
                float d1 = fmaf(ux, b01.y - b01.x, b01.x);  // (y+1, z+1)

                float w0 = fmaf(uy, c1 - c0, c0);
                float w1 = fmaf(uy, d1 - d0, d0);
                acc += fmaf(uz, w1 - w0, w0);
            }
        }
    }

    // full-warp reduction (one ray per warp)
    acc += __shfl_xor_sync(0xffffffffu, acc, 1);
    acc += __shfl_xor_sync(0xffffffffu, acc, 2);
    acc += __shfl_xor_sync(0xffffffffu, acc, 4);
    acc += __shfl_xor_sync(0xffffffffu, acc, 8);
    acc += __shfl_xor_sync(0xffffffffu, acc, 16);

    if (valid && lane == 0) {
        float s = (acc - 1024.0f * nin) * V_SCALE;  // back to v-scale sum
        out[ray] = s * raylen / (float)P;
    }
}

// ---------------------------------------------------------------------------
// Launch
// ---------------------------------------------------------------------------
extern "C" void kernel_launch(void* const* d_in, const int* in_sizes, int n_in,
                              void* d_out, int out_size) {
    const float* density = (const float*)d_in[0];
    const float* source  = (const float*)d_in[1];
    const float* target  = (const float*)d_in[2];
    const float* affine  = (const float*)d_in[3];
    const int*   npts    = (const int*)d_in[4];

    float* out = (float*)d_out;
    int nrays = in_sizes[1] / 3;

    // 1) sigmoid + quantize + transpose + u8 quad pack
    pack_kernel<<<dim3(8, 8, 32), 256>>>(density, affine);

    // 2) ray integration, one warp per ray, 256-thread blocks (8 rays/block)
    long threads = (long)nrays * 32;
    drr_kernel<<<(int)((threads + 255) / 256), 256>>>(source, target, npts,
                                                      out, nrays);
}

// round 17
// speedup vs baseline: 1.0523x; 1.0523x over previous
#include <cuda_runtime.h>
#include <cuda_fp16.h>
#include <math.h>

// ---------------------------------------------------------------------------
// DRR ray integration, GB300.
// g_vol[z][y][x] holds a 2x2 (x,y)-face quad of the regulated density,
// quantized to u8:  u = round( v * 255/0.65 ),  v = sigmoid(d - 0.3).
//   quad bytes = ( u(x,y), u(x+1,y), u(x,y+1), u(x+1,y+1) )  in one uint.
// One trilinear tap = 2 x LDG.32 (faces at z and z+1); 70 MB volume is
// mostly L2-resident. u=0 maps to v=0 so zero-padded borders are exact.
// drr: one warp per ray, issue-bound -> minimize ops/tap: PRMT column
// pairs + SIMD fp16 x-lerp (HSUB2+HFMA2 does both y-rows at once; diffs
// exact in fp16, one rounding <= 0.5u), invPm1 folded into direction.
// pack: float4 reads + tanh-sigmoid + word STS; write phase assembles
// quads from smem words via PRMT.
// ---------------------------------------------------------------------------

#define DIM 256
#define PITCH 260
#define PITCH2 (PITCH * PITCH)

#define V_SCALE (0.65f / 255.0f)      // v = u * V_SCALE
#define U_SCALE (255.0f / 0.65f)      // u = v * U_SCALE

__device__ unsigned g_vol[PITCH * PITCH * PITCH];  // ~70 MB, .bss zero-init
__device__ float    g_inv[12];                      // inv(affine)[:3,:4]

// ---------------------------------------------------------------------------
// 4x4 Gauss-Jordan inverse (single thread; runs inside pack kernel).
// ---------------------------------------------------------------------------
__device__ void invert_affine(const float* __restrict__ A) {
    float m[4][8];
#pragma unroll
    for (int r = 0; r < 4; r++)
#pragma unroll
        for (int c = 0; c < 4; c++) {
            m[r][c]     = A[r * 4 + c];
            m[r][c + 4] = (r == c) ? 1.0f : 0.0f;
        }
    for (int col = 0; col < 4; col++) {
        int piv = col;
        float best = fabsf(m[col][col]);
        for (int r = col + 1; r < 4; r++) {
            float v = fabsf(m[r][col]);
            if (v > best) { best = v; piv = r; }
        }
        if (piv != col)
            for (int c = 0; c < 8; c++) {
                float t = m[col][c]; m[col][c] = m[piv][c]; m[piv][c] = t;
            }
        float d = 1.0f / m[col][col];
        for (int c = 0; c < 8; c++) m[col][c] *= d;
        for (int r = 0; r < 4; r++) {
            if (r == col) continue;
            float f = m[r][col];
            for (int c = 0; c < 8; c++) m[r][c] -= f * m[col][c];
        }
    }
    for (int r = 0; r < 3; r++)
        for (int c = 0; c < 4; c++)
            g_inv[r * 4 + c] = m[r][c + 4];
}

// sigmoid(d - 0.3) via hardware tanh: sig = 0.5*tanh((d-0.3)/2) + 0.5
__device__ __forceinline__ float sig_fast(float d) {
    float t;
    asm("tanh.approx.f32 %0, %1;" : "=f"(t) : "f"(0.5f * (d - 0.3f)));
    return fmaf(0.5f, t, 0.5f);
}

__device__ __forceinline__ unsigned q8f(float v) {
    int u = __float2int_rn(v * U_SCALE);
    return (unsigned)min(max(u, 0), 255);
}

// pack 4 density floats -> 4 quantized bytes in one u32 (z, z+1, z+2, z+3)
__device__ __forceinline__ unsigned quant4(float4 f) {
    unsigned u0 = q8f(sig_fast(f.x));
    unsigned u1 = q8f(sig_fast(f.y));
    unsigned u2 = q8f(sig_fast(f.z));
    unsigned u3 = q8f(sig_fast(f.w));
    return u0 | (u1 << 8) | (u2 << 16) | (u3 << 24);
}

// ---------------------------------------------------------------------------
// Pack kernel: sigmoid + quantize + transpose + (x,y)-face u8-quad pack.
// Flat 256 threads. Tile x:32 (+1 halo), z:32, y:8 (+1 halo plane).
// grid = (8 x-tiles, 8 z-tiles, 32 y-groups).
// Read phase: float4 LDG (4 z at once), 3 planes batched for MLP, word STS.
// Write phase: word LDS + PRMT quad assembly (no byte-LDS).
// ---------------------------------------------------------------------------
__global__ void pack_kernel(const float* __restrict__ dens,
                            const float* __restrict__ affine) {
    int tid = threadIdx.x;
    if (blockIdx.x == 0 && blockIdx.y == 0 && blockIdx.z == 0 && tid == 0)
        invert_affine(affine);

    __shared__ unsigned char s8[9][33][36];  // [yl][x-local][z-local(pad 36)]
    const int x0 = blockIdx.x * 32;
    const int z0 = blockIdx.y * 32;
    const int y0 = blockIdx.z * 8;

    const int row   = tid >> 3;   // 0..31 : x-local row
    const int chunk = tid & 7;    // 0..7  : z float4 chunk

    // --- read phase: 9 y-planes in 3 groups of 3; each group keeps 3 (+1
    // halo) independent float4 loads in flight before any consumes. ---
#pragma unroll
    for (int yg = 0; yg < 3; yg++) {
        float4 v[3];
        float4 vh[3];
        bool ok[3], okh[3];
#pragma unroll
        for (int j = 0; j < 3; j++) {
            int yl = yg * 3 + j;
            int y  = y0 + yl;
            bool yok = (y < DIM);
            int x = x0 + row;
            ok[j] = yok;
            v[j] = ok[j]
                 ? *reinterpret_cast<const float4*>(
                       dens + ((x * DIM) + y) * DIM + z0 + 4 * chunk)
                 : make_float4(1e30f, 1e30f, 1e30f, 1e30f);
            if (tid < 8) {  // halo row x = x0 + 32
                int xh = x0 + 32;
                okh[j] = yok && (xh < DIM);
                vh[j] = okh[j]
                      ? *reinterpret_cast<const float4*>(
                            dens + ((xh * DIM) + y) * DIM + z0 + 4 * tid)
                      : make_float4(1e30f, 1e30f, 1e30f, 1e30f);
            }
        }
#pragma unroll
        for (int j = 0; j < 3; j++) {
            int yl = yg * 3 + j;
            unsigned w = ok[j] ? quant4(v[j]) : 0u;
            *reinterpret_cast<unsigned*>(&s8[yl][row][4 * chunk]) = w;
            if (tid < 8) {
                unsigned wh = okh[j] ? quant4(vh[j]) : 0u;
                *reinterpret_cast<unsigned*>(&s8[yl][32][4 * tid]) = wh;
            }
        }
    }
    __syncthreads();

    // --- write phase: word LDS + PRMT quad assembly ---
    const unsigned* W = reinterpret_cast<const unsigned*>(s8);
    const int tx = tid & 31;      // x lane (coalesced STG)
    const int zw = tid >> 5;      // 0..7 : z word (4 z-values)

#pragma unroll
    for (int yl = 0; yl < 8; yl++) {
        int yp = y0 + yl + 2;
        unsigned w0 = W[(yl * 33 + tx) * 9 + zw];            // (x  , yl  )
        unsigned w1 = W[(yl * 33 + tx + 1) * 9 + zw];        // (x+1, yl  )
        unsigned w2 = W[((yl + 1) * 33 + tx) * 9 + zw];      // (x  , yl+1)
        unsigned w3 = W[((yl + 1) * 33 + tx + 1) * 9 + zw];  // (x+1, yl+1)
#pragma unroll
        for (int k = 0; k < 4; k++) {
            int z = 4 * zw + k;
            int o = ((z0 + z + 2) * PITCH + yp) * PITCH;
            unsigned sel = 0x40u + 0x11u * (unsigned)k;  // {4+k, k}
            unsigned lo = __byte_perm(w0, w1, sel);      // (b0, b1)
            unsigned hi = __byte_perm(w2, w3, sel);      // (b2, b3)
            g_vol[o + x0 + tx + 2] = __byte_perm(lo, hi, 0x5410);
            if (x0 == 0 && tx == 0) {  // padded x=1: orig x=-1 pair
                unsigned b1 = (w0 >> (8 * k)) & 0xFFu;
                unsigned b3 = (w2 >> (8 * k)) & 0xFFu;
                g_vol[o + 1] = (b1 << 8) | (b3 << 24);
            }
        }
    }
    // padded y=1 row (orig y=-1): quad = (0,0, v(x,0), v(x+1,0))
    if (y0 == 0) {
        unsigned w2 = W[(0 * 33 + tx) * 9 + zw];
        unsigned w3 = W[(0 * 33 + tx + 1) * 9 + zw];
#pragma unroll
        for (int k = 0; k < 4; k++) {
            int z = 4 * zw + k;
            int o = ((z0 + z + 2) * PITCH + 1) * PITCH;
            unsigned sel = 0x40u + 0x11u * (unsigned)k;
            unsigned hi = __byte_perm(w2, w3, sel);
            g_vol[o + x0 + tx + 2] = hi << 16;
            if (x0 == 0 && tx == 0) {
                unsigned b3 = (w2 >> (8 * k)) & 0xFFu;
                g_vol[o + 1] = (b3 << 24);
            }
        }
    }
}

// ---------------------------------------------------------------------------
// Ray march: ONE WARP PER RAY, issue-optimized inner loop. Lane l takes
// samples p = plo+l, plo+l+32, ...; coordinates independent per tap
// (X = fma(p, d*invPm1, s)), PRMT column-pair decode + SIMD fp16 x-lerp,
// fp32 y/z lerp, full-warp shfl reduce, one per-ray affine correction.
// ---------------------------------------------------------------------------
__global__ void __launch_bounds__(256, 8)
drr_kernel(const float* __restrict__ src,
           const float* __restrict__ tgt,
           const int* __restrict__ npts,
           float* __restrict__ out,
           int nrays) {
    int t    = blockIdx.x * blockDim.x + threadIdx.x;
    int ray  = t >> 5;          // one warp per ray
    int lane = t & 31;
    bool valid = (ray < nrays);

    float acc = 0.0f;       // accumulates w = 1024 + lerp(u)
    float raylen = 0.0f;
    float nin = 0.0f;       // in-box sample count (warp-uniform)
    int P = 500;

    if (valid) {
        P = npts[0];
        float Sx = src[ray * 3 + 0], Sy = src[ray * 3 + 1], Sz = src[ray * 3 + 2];
        float Tx = tgt[ray * 3 + 0], Ty = tgt[ray * 3 + 1], Tz = tgt[ray * 3 + 2];

        float wx = Tx - Sx, wy = Ty - Sy, wz = Tz - Sz;
        raylen = sqrtf(wx * wx + wy * wy + wz * wz);

        // world -> voxel index space
        float sx = g_inv[0] * Sx + g_inv[1] * Sy + g_inv[2]  * Sz + g_inv[3];
        float sy = g_inv[4] * Sx + g_inv[5] * Sy + g_inv[6]  * Sz + g_inv[7];
        float sz = g_inv[8] * Sx + g_inv[9] * Sy + g_inv[10] * Sz + g_inv[11];
        float ex = g_inv[0] * Tx + g_inv[1] * Ty + g_inv[2]  * Tz + g_inv[3];
        float ey = g_inv[4] * Tx + g_inv[5] * Ty + g_inv[6]  * Tz + g_inv[7];
        float ez = g_inv[8] * Tx + g_inv[9] * Ty + g_inv[10] * Tz + g_inv[11];

        float dx = ex - sx, dy = ey - sy, dz = ez - sz;

        // slab-clip alpha to open support box (-1, 256), slightly widened
        float a0 = 0.0f, a1 = 1.0f;
        {
            const float lo = -1.002f, hi = 256.002f;
            float ss[3] = {sx, sy, sz};
            float dd[3] = {dx, dy, dz};
#pragma unroll
            for (int ax = 0; ax < 3; ax++) {
                float s = ss[ax], d = dd[ax];
                if (fabsf(d) < 1e-12f) {
                    if (s <= lo || s >= hi) { a0 = 1.0f; a1 = 0.0f; }
                } else {
                    float inv = 1.0f / d;
                    float ta = (lo - s) * inv;
                    float tb = (hi - s) * inv;
                    a0 = fmaxf(a0, fminf(ta, tb));
                    a1 = fminf(a1, fmaxf(ta, tb));
                }
            }
        }

        float invPm1 = 1.0f / (float)(P - 1);
        int plo = max(0, (int)ceilf(a0 * (float)(P - 1)));
        int phi = min(P - 1, (int)floorf(a1 * (float)(P - 1)));

        if (phi >= plo) {
            nin = (float)(phi - plo + 1);
            // fold invPm1 into the direction; pre-shift start by +2 padding
            float ddx = dx * invPm1, ddy = dy * invPm1, ddz = dz * invPm1;
            float sx2 = sx + 2.0f, sy2 = sy + 2.0f, sz2 = sz + 2.0f;

#pragma unroll 4
            for (int p = plo + lane; p <= phi; p += 32) {
                float a = (float)p;
                float X = fmaf(a, ddx, sx2);
                float Y = fmaf(a, ddy, sy2);
                float Z = fmaf(a, ddz, sz2);

                // coords >= ~1 by the clip, so trunc == floor
                int ix = (int)X, iy = (int)Y, iz = (int)Z;
                float ux = X - (float)ix;
                float uy = Y - (float)iy;
                float uz = Z - (float)iz;

                int base = (iz * PITCH + iy) * PITCH + ix;
                unsigned q0 = __ldg(&g_vol[base]);            // face at z
                unsigned q1 = __ldg(&g_vol[base + PITCH2]);   // face at z+1

                // column pairs: lo = (1024+u(x,y),  1024+u(x,y+1))
                //               hi = (1024+u(x+1,y),1024+u(x+1,y+1))
                unsigned lo0 = __byte_perm(q0, 0x64646464u, 0x5240);
                unsigned hi0 = __byte_perm(q0, 0x64646464u, 0x5341);
                unsigned lo1 = __byte_perm(q1, 0x64646464u, 0x5240);
                unsigned hi1 = __byte_perm(q1, 0x64646464u, 0x5341);

                __half2 l0 = *reinterpret_cast<__half2*>(&lo0);
                __half2 h0 = *reinterpret_cast<__half2*>(&hi0);
                __half2 l1 = *reinterpret_cast<__half2*>(&lo1);
                __half2 h1 = *reinterpret_cast<__half2*>(&hi1);

                // SIMD x-lerp: both y-rows at once (diffs exact in fp16,
                // one fused rounding <= 0.5u)
                __half2 ux2 = __float2half2_rn(ux);
                __half2 xl0 = __hfma2(ux2, __hsub2(h0, l0), l0);
                __half2 xl1 = __hfma2(ux2, __hsub2(h1, l1), l1);

                float2 f0 = __half22float2(xl0);
                float2 f1 = __half22float2(xl1);

                // y-lerp, z-lerp in fp32
                float w0 = fmaf(uy, f0.y - f0.x, f0.x);
                float w1 = fmaf(uy, f1.y - f1.x, f1.x);
                acc += fmaf(uz, w1 - w0, w0);
            }
        }
    }

    // full-warp reduction (one ray per warp)
    acc += __shfl_xor_sync(0xffffffffu, acc, 1);
    acc += __shfl_xor_sync(0xffffffffu, acc, 2);
    acc += __shfl_xor_sync(0xffffffffu, acc, 4);
    acc += __shfl_xor_sync(0xffffffffu, acc, 8);
    acc += __shfl_xor_sync(0xffffffffu, acc, 16);

    if (valid && lane == 0) {
        float s = (acc - 1024.0f * nin) * V_SCALE;  // back to v-scale sum
        out[ray] = s * raylen / (float)P;
    }
}

// ---------------------------------------------------------------------------
// Launch
// ---------------------------------------------------------------------------
extern "C" void kernel_launch(void* const* d_in, const int* in_sizes, int n_in,
                              void* d_out, int out_size) {
    const float* density = (const float*)d_in[0];
    const float* source  = (const float*)d_in[1];
    const float* target  = (const float*)d_in[2];
    const float* affine  = (const float*)d_in[3];
    const int*   npts    = (const int*)d_in[4];

    float* out = (float*)d_out;
    int nrays = in_sizes[1] / 3;

    // 1) sigmoid + quantize + transpose + u8 quad pack
    pack_kernel<<<dim3(8, 8, 32), 256>>>(density, affine);

    // 2) ray integration, one warp per ray, 256-thread blocks (8 rays/block)
    long threads = (long)nrays * 32;
    drr_kernel<<<(int)((threads + 255) / 256), 256>>>(source, target, npts,
                                                      out, nrays);
}